// round 2
// baseline (speedup 1.0000x reference)
#include <cuda_runtime.h>
#include <math.h>

#define BB 64
#define QQ 4096
#define NN 256
#define NC 20          // foreground classes
#define NL 21          // logits per query (NC + 1)
#define QT 32          // q-tile per block

#define COST_CLASS  1.0f
#define COST_CENTER 5.0f
#define COST_IOU    2.0f
#define INF_REPLACE 1000000.0f
// Fast-path gate on the EXPANDED-form d^2 (|p|^2 - 2 p.t + |t|^2). Magnitudes
// reach ~1.5e4 so rounding error is <~5e-3; gate at 4 + 1/16 so the fast path
// only ever fires when true d^2 > 4 (=> center cost inf => INF_REPLACE exactly).
// Borderline elements fall to the slow path which recomputes (p-t) directly,
// matching reference arithmetic bit-for-bit on the threshold decision.
#define THR_FAST    4.0625f

__global__ __launch_bounds__(256) void matcher_kernel(
    const float* __restrict__ logits,    // [B, Q, 21]
    const float* __restrict__ pboxes,    // [B, Q, 6]
    const int*   __restrict__ labels,    // [B, N]
    const float* __restrict__ tboxes,    // [B, N, 6]
    float*       __restrict__ out)       // [B, Q, N]
{
    const int blocks_per_b = QQ / QT;
    const int b  = blockIdx.x / blocks_per_b;
    const int q0 = (blockIdx.x % blocks_per_b) * QT;
    const int t  = threadIdx.x;
    const int tgroup = t >> 6;      // 0..3 : which 8-row q slice
    const int n4     = t & 63;      // target quad: covers n = 4*n4 .. 4*n4+3

    __shared__ float  s_lg[QT * NL];
    __shared__ float  s_probs[QT][NC];
    __shared__ float4 s_pcn[QT];    // (pcx, pcy, pcz, |pc|^2)
    __shared__ float4 s_ps[QT];     // (psx, psy, psz, vol1)

    // ---- per-thread target constants for the expanded-form gate ----
    float Ax[4], Ay[4], Az[4], Kk[4];   // -2*tc, |tc|^2
    {
        const float* tb = tboxes + ((size_t)b * NN + 4 * n4) * 6;
        #pragma unroll
        for (int j = 0; j < 4; j++) {
            float x = tb[j*6+0], y = tb[j*6+1], z = tb[j*6+2];
            Ax[j] = -2.0f * x; Ay[j] = -2.0f * y; Az[j] = -2.0f * z;
            Kk[j] = x*x + y*y + z*z;
        }
    }

    // ---- coalesced stage of logits; small stage of pred boxes ----
    {
        const float* lg = logits + ((size_t)b * QQ + q0) * NL;
        for (int i = t; i < QT * NL; i += 256) s_lg[i] = lg[i];
    }
    if (t < QT) {
        const float* pb = pboxes + ((size_t)b * QQ + q0 + t) * 6;
        float x = pb[0], y = pb[1], z = pb[2];
        float sx = pb[3], sy = pb[4], sz = pb[5];
        s_pcn[t] = make_float4(x, y, z, x*x + y*y + z*z);
        s_ps[t]  = make_float4(sx, sy, sz, sx*sy*sz);
    }
    __syncthreads();

    // ---- softmax: one thread per q ----
    if (t < QT) {
        float e[NL]; float s = 0.0f;
        #pragma unroll
        for (int c = 0; c < NL; c++) { e[c] = expf(s_lg[t*NL + c]); s += e[c]; }
        float inv = 1.0f / s;
        #pragma unroll
        for (int c = 0; c < NC; c++) s_probs[t][c] = e[c] * inv;
    }
    __syncthreads();

    // ---- main loop: 8 q-rows per thread, float4 store per row ----
    float4* orow = (float4*)(out + (((size_t)b * QQ + q0 + tgroup * 8) * NN) + 4 * n4);
    const int row_stride4 = NN / 4;   // float4 stride between q rows

    #pragma unroll
    for (int u = 0; u < 8; u++) {
        const int qi = tgroup * 8 + u;
        const float4 p = s_pcn[qi];
        const float tq = THR_FAST - p.w;   // far iff  m_j > tq

        const float m0 = fmaf(Ax[0], p.x, fmaf(Ay[0], p.y, fmaf(Az[0], p.z, Kk[0])));
        const float m1 = fmaf(Ax[1], p.x, fmaf(Ay[1], p.y, fmaf(Az[1], p.z, Kk[1])));
        const float m2 = fmaf(Ax[2], p.x, fmaf(Ay[2], p.y, fmaf(Az[2], p.z, Kk[2])));
        const float m3 = fmaf(Ax[3], p.x, fmaf(Ay[3], p.y, fmaf(Az[3], p.z, Kk[3])));

        float4 r;
        if (m0 > tq && m1 > tq && m2 > tq && m3 > tq) {
            r = make_float4(INF_REPLACE, INF_REPLACE, INF_REPLACE, INF_REPLACE);
        } else {
            // rare slow path: exact reference arithmetic per element
            float rv[4];
            const float mm[4] = {m0, m1, m2, m3};
            #pragma unroll
            for (int j = 0; j < 4; j++) {
                if (mm[j] > tq) { rv[j] = INF_REPLACE; continue; }
                const float tcx = -0.5f * Ax[j];
                const float tcy = -0.5f * Ay[j];
                const float tcz = -0.5f * Az[j];
                const float dx = p.x - tcx, dy = p.y - tcy, dz = p.z - tcz;
                const float d2 = dx*dx + dy*dy + dz*dz;
                const float dist = sqrtf(d2);
                if (dist > 2.0f) { rv[j] = INF_REPLACE; continue; }

                const int nn = 4 * n4 + j;
                const float* tbj = tboxes + ((size_t)b * NN + nn) * 6;
                const float tsx = tbj[3], tsy = tbj[4], tsz = tbj[5];
                const float4 ps = s_ps[qi];

                float ix = fminf(p.x + 0.5f*ps.x, tcx + 0.5f*tsx)
                         - fmaxf(p.x - 0.5f*ps.x, tcx - 0.5f*tsx);
                float iy = fminf(p.y + 0.5f*ps.y, tcy + 0.5f*tsy)
                         - fmaxf(p.y - 0.5f*ps.y, tcy - 0.5f*tsy);
                float iz = fminf(p.z + 0.5f*ps.z, tcz + 0.5f*tsz)
                         - fmaxf(p.z - 0.5f*ps.z, tcz - 0.5f*tsz);
                ix = fmaxf(ix, 0.0f); iy = fmaxf(iy, 0.0f); iz = fmaxf(iz, 0.0f);

                const float inter = ix * iy * iz;
                const float vol2  = tsx * tsy * tsz;
                const float uni   = ps.w + vol2 - inter;
                const float iou   = (uni > 0.0f) ? (inter / uni) : 0.0f;

                const int   lbl = labels[b * NN + nn];
                const float cls = -s_probs[qi][lbl];
                rv[j] = COST_CLASS * cls + COST_CENTER * dist + COST_IOU * (1.0f - iou);
            }
            r = make_float4(rv[0], rv[1], rv[2], rv[3]);
        }
        orow[(size_t)u * row_stride4] = r;
    }
}

extern "C" void kernel_launch(void* const* d_in, const int* in_sizes, int n_in,
                              void* d_out, int out_size)
{
    const float* logits = (const float*)d_in[0];  // [B,Q,21]
    const float* pboxes = (const float*)d_in[1];  // [B,Q,6]
    const int*   labels = (const int*)  d_in[2];  // [B,N]
    const float* tboxes = (const float*)d_in[3];  // [B,N,6]
    float*       out    = (float*)d_out;          // [B,Q,N]

    dim3 grid(BB * (QQ / QT));
    dim3 block(256);
    matcher_kernel<<<grid, block>>>(logits, pboxes, labels, tboxes, out);
}

// round 3
// speedup vs baseline: 1.0110x; 1.0110x over previous
#include <cuda_runtime.h>
#include <math.h>

#define BB 64
#define QQ 4096
#define NN 256
#define NC 20          // foreground classes
#define NL 21          // logits per query (NC + 1)
#define QT 32          // q-tile per block

#define COST_CLASS  1.0f
#define COST_CENTER 5.0f
#define COST_IOU    2.0f
#define INF_REPLACE 1000000.0f
// Fast-path gate on the EXPANDED-form d^2 (|p|^2 - 2 p.t + |t|^2). Magnitudes
// reach ~1.5e4 so rounding error is <~5e-3; gate at 4 + 1/16 so the fast path
// only ever fires when true d^2 > 4 (=> center cost inf => INF_REPLACE exactly).
// Borderline elements fall to the slow path which recomputes (p-t) directly,
// matching reference arithmetic bit-for-bit on the threshold decision.
#define THR_FAST    4.0625f

__global__ __launch_bounds__(256) void matcher_kernel(
    const float* __restrict__ logits,    // [B, Q, 21]
    const float* __restrict__ pboxes,    // [B, Q, 6]
    const int*   __restrict__ labels,    // [B, N]
    const float* __restrict__ tboxes,    // [B, N, 6]
    float*       __restrict__ out)       // [B, Q, N]
{
    const int blocks_per_b = QQ / QT;
    const int b  = blockIdx.x / blocks_per_b;
    const int q0 = (blockIdx.x % blocks_per_b) * QT;
    const int t  = threadIdx.x;
    const int tgroup = t >> 6;      // 0..3 : which 8-row q slice
    const int n4     = t & 63;      // target quad: covers n = 4*n4 .. 4*n4+3

    __shared__ float  s_lg[QT * NL];
    __shared__ float  s_probs[QT][NC];
    __shared__ float4 s_pcn[QT];    // (pcx, pcy, pcz, |pc|^2)
    __shared__ float4 s_ps[QT];     // (psx, psy, psz, vol1)

    // ---- per-thread target constants for the expanded-form gate ----
    float Ax[4], Ay[4], Az[4], Kk[4];   // -2*tc, |tc|^2
    {
        const float* tb = tboxes + ((size_t)b * NN + 4 * n4) * 6;
        #pragma unroll
        for (int j = 0; j < 4; j++) {
            float x = tb[j*6+0], y = tb[j*6+1], z = tb[j*6+2];
            Ax[j] = -2.0f * x; Ay[j] = -2.0f * y; Az[j] = -2.0f * z;
            Kk[j] = x*x + y*y + z*z;
        }
    }

    // ---- coalesced stage of logits; small stage of pred boxes ----
    {
        const float* lg = logits + ((size_t)b * QQ + q0) * NL;
        for (int i = t; i < QT * NL; i += 256) s_lg[i] = lg[i];
    }
    if (t < QT) {
        const float* pb = pboxes + ((size_t)b * QQ + q0 + t) * 6;
        float x = pb[0], y = pb[1], z = pb[2];
        float sx = pb[3], sy = pb[4], sz = pb[5];
        s_pcn[t] = make_float4(x, y, z, x*x + y*y + z*z);
        s_ps[t]  = make_float4(sx, sy, sz, sx*sy*sz);
    }
    __syncthreads();

    // ---- softmax: one thread per q ----
    if (t < QT) {
        float e[NL]; float s = 0.0f;
        #pragma unroll
        for (int c = 0; c < NL; c++) { e[c] = expf(s_lg[t*NL + c]); s += e[c]; }
        float inv = 1.0f / s;
        #pragma unroll
        for (int c = 0; c < NC; c++) s_probs[t][c] = e[c] * inv;
    }
    __syncthreads();

    // ---- main loop: 8 q-rows per thread, float4 store per row ----
    float4* orow = (float4*)(out + (((size_t)b * QQ + q0 + tgroup * 8) * NN) + 4 * n4);
    const int row_stride4 = NN / 4;   // float4 stride between q rows

    #pragma unroll
    for (int u = 0; u < 8; u++) {
        const int qi = tgroup * 8 + u;
        const float4 p = s_pcn[qi];
        const float tq = THR_FAST - p.w;   // far iff  m_j > tq

        const float m0 = fmaf(Ax[0], p.x, fmaf(Ay[0], p.y, fmaf(Az[0], p.z, Kk[0])));
        const float m1 = fmaf(Ax[1], p.x, fmaf(Ay[1], p.y, fmaf(Az[1], p.z, Kk[1])));
        const float m2 = fmaf(Ax[2], p.x, fmaf(Ay[2], p.y, fmaf(Az[2], p.z, Kk[2])));
        const float m3 = fmaf(Ax[3], p.x, fmaf(Ay[3], p.y, fmaf(Az[3], p.z, Kk[3])));

        float4 r;
        if (m0 > tq && m1 > tq && m2 > tq && m3 > tq) {
            r = make_float4(INF_REPLACE, INF_REPLACE, INF_REPLACE, INF_REPLACE);
        } else {
            // rare slow path: exact reference arithmetic per element
            float rv[4];
            const float mm[4] = {m0, m1, m2, m3};
            #pragma unroll
            for (int j = 0; j < 4; j++) {
                if (mm[j] > tq) { rv[j] = INF_REPLACE; continue; }
                const float tcx = -0.5f * Ax[j];
                const float tcy = -0.5f * Ay[j];
                const float tcz = -0.5f * Az[j];
                const float dx = p.x - tcx, dy = p.y - tcy, dz = p.z - tcz;
                const float d2 = dx*dx + dy*dy + dz*dz;
                const float dist = sqrtf(d2);
                if (dist > 2.0f) { rv[j] = INF_REPLACE; continue; }

                const int nn = 4 * n4 + j;
                const float* tbj = tboxes + ((size_t)b * NN + nn) * 6;
                const float tsx = tbj[3], tsy = tbj[4], tsz = tbj[5];
                const float4 ps = s_ps[qi];

                float ix = fminf(p.x + 0.5f*ps.x, tcx + 0.5f*tsx)
                         - fmaxf(p.x - 0.5f*ps.x, tcx - 0.5f*tsx);
                float iy = fminf(p.y + 0.5f*ps.y, tcy + 0.5f*tsy)
                         - fmaxf(p.y - 0.5f*ps.y, tcy - 0.5f*tsy);
                float iz = fminf(p.z + 0.5f*ps.z, tcz + 0.5f*tsz)
                         - fmaxf(p.z - 0.5f*ps.z, tcz - 0.5f*tsz);
                ix = fmaxf(ix, 0.0f); iy = fmaxf(iy, 0.0f); iz = fmaxf(iz, 0.0f);

                const float inter = ix * iy * iz;
                const float vol2  = tsx * tsy * tsz;
                const float uni   = ps.w + vol2 - inter;
                const float iou   = (uni > 0.0f) ? (inter / uni) : 0.0f;

                const int   lbl = labels[b * NN + nn];
                const float cls = -s_probs[qi][lbl];
                rv[j] = COST_CLASS * cls + COST_CENTER * dist + COST_IOU * (1.0f - iou);
            }
            r = make_float4(rv[0], rv[1], rv[2], rv[3]);
        }
        orow[(size_t)u * row_stride4] = r;
    }
}

extern "C" void kernel_launch(void* const* d_in, const int* in_sizes, int n_in,
                              void* d_out, int out_size)
{
    const float* logits = (const float*)d_in[0];  // [B,Q,21]
    const float* pboxes = (const float*)d_in[1];  // [B,Q,6]
    const int*   labels = (const int*)  d_in[2];  // [B,N]
    const float* tboxes = (const float*)d_in[3];  // [B,N,6]
    float*       out    = (float*)d_out;          // [B,Q,N]

    dim3 grid(BB * (QQ / QT));
    dim3 block(256);
    matcher_kernel<<<grid, block>>>(logits, pboxes, labels, tboxes, out);
}